// round 3
// baseline (speedup 1.0000x reference)
#include <cuda_runtime.h>
#include <cuda_fp16.h>
#include <math.h>

#define BB   64
#define VV   2048
#define ENCD 128
#define TT   100
#define EMBD 256
#define DECD 512
#define ATTD 256
#define NVOC 29
#define XD   384   // EMB + ENC

#define PRED_OFF  0
#define ALPHA_OFF (BB*TT*NVOC)            // 185600
#define LEN_OFF   (ALPHA_OFF + BB*TT*VV)  // 13292800

// ---------------- scratch (device globals; no allocation allowed) ----------
__device__ __half g_enc_att_h[BB*VV*ATTD];  // 64 MB fp16: enc @ W_enc.T + b_enc
__device__ __half g_enc_h[BB*VV*ENCD];      // 32 MB fp16 copy of encoder_output
__device__ float  g_hbuf[2][BB*DECD];       // ping-pong h
__device__ float  g_c[BB*DECD];
__device__ float  g_dec_att[BB*ATTD];
__device__ float  g_gate[BB*ENCD];
__device__ float  g_x[BB*XD];               // [emb_t , gate*awe]

__device__ __forceinline__ float sigf(float x) { return 1.f/(1.f+__expf(-x)); }

// ============================================================================
// Setup A: mean_enc -> h0,c0 ; write caption_lengths to out tail
// ============================================================================
__global__ void s_init(const float* __restrict__ enc, const int* __restrict__ lens,
                       const float* __restrict__ Wih_, const float* __restrict__ bih_,
                       const float* __restrict__ Wic_, const float* __restrict__ bic_,
                       float* __restrict__ out)
{
    int b = blockIdx.x, tid = threadIdx.x;
    __shared__ float red[16*128];
    __shared__ float mean[128];
    int vr = tid >> 5, l = tid & 31;

    float4 acc = make_float4(0.f,0.f,0.f,0.f);
    for (int v = vr; v < VV; v += 16) {
        float4 e = *(const float4*)&enc[((size_t)(b*VV + v))*ENCD + l*4];
        acc.x += e.x; acc.y += e.y; acc.z += e.z; acc.w += e.w;
    }
    *(float4*)&red[vr*128 + l*4] = acc;
    __syncthreads();
    if (tid < 128) {
        float s = 0.f;
        #pragma unroll
        for (int i = 0; i < 16; i++) s += red[i*128 + tid];
        mean[tid] = s * (1.f/(float)VV);
    }
    __syncthreads();
    float ha = bih_[tid], ca = bic_[tid];
    const float* wh = Wih_ + (size_t)tid*ENCD;
    const float* wc = Wic_ + (size_t)tid*ENCD;
    #pragma unroll 4
    for (int k = 0; k < ENCD; k++) {
        float mk = mean[k];
        ha += mk * wh[k];
        ca += mk * wc[k];
    }
    g_hbuf[0][b*DECD + tid] = ha;
    g_c[b*DECD + tid] = ca;
    if (tid == 0) out[LEN_OFF + b] = (float)lens[b];
}

// ============================================================================
// Setup B: enc_att(fp16) = enc @ W_enc.T + b_enc ; also emit fp16 enc copy
// grid(4096), block(256), dyn smem ~166KB.
// ============================================================================
#define EA_SMEM ((128*264 + 128*68)*4)
__global__ void __launch_bounds__(256)
s_encatt(const float* __restrict__ enc, const float* __restrict__ Wenc,
         const float* __restrict__ benc)
{
    extern __shared__ float sm[];
    float* Wt = sm;             // [128][264] : Wt[k][a]
    float* Et = sm + 128*264;   // [128][68]  : Et[k][r]
    int tid = threadIdx.x;
    int rowbase = blockIdx.x * 32;

    for (int i = tid; i < 256*128; i += 256) {
        int k = i & 127, a = i >> 7;
        Wt[k*264 + a] = Wenc[a*128 + k];
    }
    for (int i = tid; i < 32*128; i += 256) {
        int k = i & 127, r = i >> 7;
        Et[k*68 + r] = enc[(size_t)(rowbase + r)*128 + k];
    }
    __syncthreads();

    // fp16 copy of enc for this tile
    for (int i = tid; i < 32*128; i += 256) {
        int r = i >> 7, k = i & 127;
        g_enc_h[(size_t)(rowbase + r)*ENCD + k] = __float2half_rn(Et[k*68 + r]);
    }

    int tr = tid >> 5, ta = tid & 31;
    int r0 = tr*4, a0 = ta*8;
    float acc[4][8];
    #pragma unroll
    for (int i = 0; i < 4; i++)
        #pragma unroll
        for (int j = 0; j < 8; j++) acc[i][j] = 0.f;

    #pragma unroll 4
    for (int k = 0; k < 128; k++) {
        float4 rf = *(const float4*)&Et[k*68 + r0];
        float4 a4 = *(const float4*)&Wt[k*264 + a0];
        float4 b4 = *(const float4*)&Wt[k*264 + a0 + 4];
        float rr[4] = {rf.x, rf.y, rf.z, rf.w};
        float aa[8] = {a4.x,a4.y,a4.z,a4.w,b4.x,b4.y,b4.z,b4.w};
        #pragma unroll
        for (int i = 0; i < 4; i++)
            #pragma unroll
            for (int j = 0; j < 8; j++) acc[i][j] += rr[i]*aa[j];
    }
    float4 be0 = *(const float4*)&benc[a0];
    float4 be1 = *(const float4*)&benc[a0+4];
    float bb[8] = {be0.x,be0.y,be0.z,be0.w,be1.x,be1.y,be1.z,be1.w};
    #pragma unroll
    for (int i = 0; i < 4; i++) {
        size_t base = (size_t)(rowbase + r0 + i)*ATTD + a0;
        __half2 h[4];
        #pragma unroll
        for (int j = 0; j < 4; j++)
            h[j] = __floats2half2_rn(acc[i][2*j] + bb[2*j], acc[i][2*j+1] + bb[2*j+1]);
        *(uint4*)&g_enc_att_h[base] = *(uint4*)h;
    }
}

// ============================================================================
// K1: dec_att = h@W_dec.T+b ; gate = sig(h@W_beta.T+b) ; pred_{t-1}=h@W_final.T+b
// ============================================================================
__global__ void __launch_bounds__(256)
k1_head(int t,
        const float* __restrict__ Wdec, const float* __restrict__ bdec,
        const float* __restrict__ Wbeta, const float* __restrict__ bbeta,
        const float* __restrict__ Wfin, const float* __restrict__ bfin,
        const int* __restrict__ lens, float* __restrict__ out)
{
    __shared__ float hT[512*17];
    int tid = threadIdx.x;
    int p = t & 1;
    int bg = blockIdx.y;
    int rr = blockIdx.x*16 + (tid >> 4);
    int lane = tid & 15;
    int b = bg*16 + lane;

    const float* hsrc = g_hbuf[p];
    for (int i = tid; i < 16*512; i += 256) {
        int bl = i >> 9, k = i & 511;
        hT[k*17 + bl] = hsrc[(bg*16 + bl)*DECD + k];
    }
    __syncthreads();

    const float* wrow = nullptr; float bias = 0.f;
    if (rr < 256)      { wrow = Wdec  + (size_t)rr*DECD;       bias = bdec[rr]; }
    else if (rr < 384) { wrow = Wbeta + (size_t)(rr-256)*DECD; bias = bbeta[rr-256]; }
    else if (rr < 384+NVOC) { wrow = Wfin + (size_t)(rr-384)*DECD; bias = bfin[rr-384]; }

    if (wrow) {
        float acc = bias;
        #pragma unroll 4
        for (int k = 0; k < 512; k += 4) {
            float4 w = *(const float4*)&wrow[k];
            acc += w.x*hT[(k  )*17 + lane] + w.y*hT[(k+1)*17 + lane]
                 + w.z*hT[(k+2)*17 + lane] + w.w*hT[(k+3)*17 + lane];
        }
        if (rr < 256) {
            g_dec_att[b*ATTD + rr] = acc;
        } else if (rr < 384) {
            g_gate[b*ENCD + (rr-256)] = sigf(acc);
        } else {
            if (t > 0 && (t-1) < lens[b])
                out[PRED_OFF + ((size_t)b*TT + (t-1))*NVOC + (rr-384)] = acc;
        }
    }
}

// ============================================================================
// K23 fused: scores (fp16 enc_att) -> softmax -> alphas out -> awe (fp16 enc)
//            -> x = [emb, gate*awe].   grid(64), block(512). Length-masked.
// ============================================================================
__global__ void __launch_bounds__(512)
k23_attn(int t, const int* __restrict__ captions, const float* __restrict__ embW,
         const float* __restrict__ wfull, const int* __restrict__ lens,
         float* __restrict__ out)
{
    int b = blockIdx.x;
    if (t >= lens[b]) return;
    int tid = threadIdx.x;
    int warp = tid >> 5, l = tid & 31;

    __shared__ float s[VV];
    __shared__ float red[16*128];
    __shared__ float wmax[16], wsum[16], fin[2];

    // ---- Phase A: scores[v] = sum_a relu(enc_att[v,a] + dec_att[a]) * w[a]
    int a0 = l*8;
    float d[8], w[8];
    {
        float4 dd0 = *(const float4*)&g_dec_att[b*ATTD + a0];
        float4 dd1 = *(const float4*)&g_dec_att[b*ATTD + a0 + 4];
        float4 ww0 = *(const float4*)&wfull[a0];
        float4 ww1 = *(const float4*)&wfull[a0 + 4];
        d[0]=dd0.x; d[1]=dd0.y; d[2]=dd0.z; d[3]=dd0.w;
        d[4]=dd1.x; d[5]=dd1.y; d[6]=dd1.z; d[7]=dd1.w;
        w[0]=ww0.x; w[1]=ww0.y; w[2]=ww0.z; w[3]=ww0.w;
        w[4]=ww1.x; w[5]=ww1.y; w[6]=ww1.z; w[7]=ww1.w;
    }
    const __half* ea = g_enc_att_h + (size_t)b*VV*ATTD;

    // 16 warps, each covers 128 v-rows, 2 rows in flight
    for (int i = 0; i < 128; i += 2) {
        int v0 = (i  )*16 + warp;
        int v1 = (i+1)*16 + warp;
        uint4 q0 = *(const uint4*)&ea[(size_t)v0*ATTD + a0];
        uint4 q1 = *(const uint4*)&ea[(size_t)v1*ATTD + a0];
        const __half2* h0 = (const __half2*)&q0;
        const __half2* h1 = (const __half2*)&q1;
        float s0 = 0.f, s1 = 0.f;
        #pragma unroll
        for (int j = 0; j < 4; j++) {
            float2 e0 = __half22float2(h0[j]);
            float2 e1 = __half22float2(h1[j]);
            s0 += fmaxf(e0.x + d[2*j],   0.f)*w[2*j]
                + fmaxf(e0.y + d[2*j+1], 0.f)*w[2*j+1];
            s1 += fmaxf(e1.x + d[2*j],   0.f)*w[2*j]
                + fmaxf(e1.y + d[2*j+1], 0.f)*w[2*j+1];
        }
        #pragma unroll
        for (int o = 16; o; o >>= 1) {
            s0 += __shfl_xor_sync(0xffffffffu, s0, o);
            s1 += __shfl_xor_sync(0xffffffffu, s1, o);
        }
        if (l == 0) { s[v0] = s0; s[v1] = s1; }
    }
    __syncthreads();

    // ---- Phase B: softmax over V (in smem)
    float m = -1e30f;
    for (int v = tid; v < VV; v += 512) m = fmaxf(m, s[v]);
    #pragma unroll
    for (int o = 16; o; o >>= 1) m = fmaxf(m, __shfl_xor_sync(0xffffffffu, m, o));
    if (l == 0) wmax[warp] = m;
    __syncthreads();
    if (tid == 0) {
        float mm = wmax[0];
        #pragma unroll
        for (int i = 1; i < 16; i++) mm = fmaxf(mm, wmax[i]);
        fin[0] = mm;
    }
    __syncthreads();
    float gmax = fin[0];

    float sum = 0.f;
    for (int v = tid; v < VV; v += 512) { float e = __expf(s[v] - gmax); s[v] = e; sum += e; }
    #pragma unroll
    for (int o = 16; o; o >>= 1) sum += __shfl_xor_sync(0xffffffffu, sum, o);
    if (l == 0) wsum[warp] = sum;
    __syncthreads();
    if (tid == 0) {
        float ss = 0.f;
        #pragma unroll
        for (int i = 0; i < 16; i++) ss += wsum[i];
        fin[1] = 1.f/ss;
    }
    __syncthreads();
    float inv = fin[1];

    float* aout = out + ALPHA_OFF + ((size_t)b*TT + t)*VV;
    for (int v = tid; v < VV; v += 512) { float a = s[v]*inv; s[v] = a; aout[v] = a; }
    __syncthreads();

    // ---- Phase C: awe = alpha . enc  (fp16 enc), then gate & x
    const __half* eh = g_enc_h + (size_t)b*VV*ENCD;
    int vr = warp;
    float4 acc = make_float4(0.f,0.f,0.f,0.f);
    for (int v = vr; v < VV; v += 64) {
        #pragma unroll
        for (int u = 0; u < 4; u++) {
            int vv = v + u*16;
            float av = s[vv];
            uint2 q = *(const uint2*)&eh[(size_t)vv*ENCD + l*4];
            float2 e0 = __half22float2(((const __half2*)&q)[0]);
            float2 e1 = __half22float2(((const __half2*)&q)[1]);
            acc.x += av*e0.x; acc.y += av*e0.y; acc.z += av*e1.x; acc.w += av*e1.y;
        }
    }
    *(float4*)&red[vr*128 + l*4] = acc;
    __syncthreads();
    if (tid < 128) {
        float aw = 0.f;
        #pragma unroll
        for (int i = 0; i < 16; i++) aw += red[i*128 + tid];
        aw *= g_gate[b*ENCD + tid];
        g_x[b*XD + EMBD + tid] = aw;
    }
    int cap = captions[b*TT + t];
    if (tid < EMBD) g_x[b*XD + tid] = embW[cap*EMBD + tid];
}

// ============================================================================
// K4: LSTM cell.
// ============================================================================
__global__ void __launch_bounds__(256)
k4_lstm(int t,
        const float* __restrict__ Wih, const float* __restrict__ bih,
        const float* __restrict__ Whh, const float* __restrict__ bhh,
        const int* __restrict__ lens)
{
    int jc = blockIdx.x;
    int bh = blockIdx.y;
    int tid = threadIdx.x;
    int p = t & 1;
    int jbase = jc*8;
    int b0 = bh*32;

    if (t >= lens[b0]) {         // lens sorted desc -> whole half masked
        int jj = tid >> 5, bl = tid & 31;
        int idx = (b0 + bl)*DECD + jbase + jj;
        g_hbuf[1-p][idx] = g_hbuf[p][idx];
        return;
    }

    __shared__ float zt[128*36];
    __shared__ float ws[32*132];
    __shared__ float gs[32*33];

    int r = tid >> 3;
    int lane = tid & 7;
    int bl0 = lane*4;
    int grow = (r >> 3)*DECD + jbase + (r & 7);

    float acc0=0.f, acc1=0.f, acc2=0.f, acc3=0.f;
    const float* hsrc = g_hbuf[p];

    for (int kt = 0; kt < 7; kt++) {
        for (int i = tid; i < 32*128; i += 256) {
            int bl = i >> 7, k = i & 127;
            float v;
            if (kt < 3) v = g_x[(b0 + bl)*XD + kt*128 + k];
            else        v = hsrc[(b0 + bl)*DECD + (kt-3)*128 + k];
            zt[k*36 + bl] = v;
        }
        const float* Wp = (kt < 3) ? Wih : Whh;
        int kstride = (kt < 3) ? XD : DECD;
        int kb = (kt < 3) ? kt*128 : (kt-3)*128;
        for (int i = tid; i < 32*128; i += 256) {
            int rr2 = i >> 7, k = i & 127;
            int gr = (rr2 >> 3)*DECD + jbase + (rr2 & 7);
            ws[rr2*132 + k] = Wp[(size_t)gr*kstride + kb + k];
        }
        __syncthreads();
        #pragma unroll 4
        for (int k = 0; k < 128; k += 4) {
            float4 w4 = *(const float4*)&ws[r*132 + k];
            float4 za = *(const float4*)&zt[(k  )*36 + bl0];
            float4 zb = *(const float4*)&zt[(k+1)*36 + bl0];
            float4 zc = *(const float4*)&zt[(k+2)*36 + bl0];
            float4 zd = *(const float4*)&zt[(k+3)*36 + bl0];
            acc0 += w4.x*za.x + w4.y*zb.x + w4.z*zc.x + w4.w*zd.x;
            acc1 += w4.x*za.y + w4.y*zb.y + w4.z*zc.y + w4.w*zd.y;
            acc2 += w4.x*za.z + w4.y*zb.z + w4.z*zc.z + w4.w*zd.z;
            acc3 += w4.x*za.w + w4.y*zb.w + w4.z*zc.w + w4.w*zd.w;
        }
        __syncthreads();
    }
    float bias = bih[grow] + bhh[grow];
    gs[r*33 + bl0 + 0] = acc0 + bias;
    gs[r*33 + bl0 + 1] = acc1 + bias;
    gs[r*33 + bl0 + 2] = acc2 + bias;
    gs[r*33 + bl0 + 3] = acc3 + bias;
    __syncthreads();

    {
        int jj = tid >> 5, bl = tid & 31;
        int b = b0 + bl;
        int hidx = b*DECD + jbase + jj;
        if (t < lens[b]) {
            float gi = gs[( 0 + jj)*33 + bl];
            float gf = gs[( 8 + jj)*33 + bl];
            float gg = gs[(16 + jj)*33 + bl];
            float go = gs[(24 + jj)*33 + bl];
            float si = sigf(gi), sf = sigf(gf), so = sigf(go);
            float tg = tanhf(gg);
            float cn = sf * g_c[hidx] + si * tg;
            float hn = so * tanhf(cn);
            g_c[hidx] = cn;
            g_hbuf[1-p][hidx] = hn;
        } else {
            g_hbuf[1-p][hidx] = g_hbuf[p][hidx];
        }
    }
}

// ============================================================================
extern "C" void kernel_launch(void* const* d_in, const int* in_sizes, int n_in,
                              void* d_out, int out_size)
{
    const float* enc      = (const float*)d_in[0];
    const int*   captions = (const int*)  d_in[1];
    const int*   lens     = (const int*)  d_in[2];
    const float* embW     = (const float*)d_in[3];
    const float* Wenc     = (const float*)d_in[4];
    const float* benc     = (const float*)d_in[5];
    const float* Wdec     = (const float*)d_in[6];
    const float* bdec     = (const float*)d_in[7];
    const float* wfull    = (const float*)d_in[8];
    // d_in[9] = b_full : dropped (softmax shift-invariant)
    const float* Wih      = (const float*)d_in[10];
    const float* bih      = (const float*)d_in[11];
    const float* Whh      = (const float*)d_in[12];
    const float* bhh      = (const float*)d_in[13];
    const float* Winith   = (const float*)d_in[14];
    const float* binith   = (const float*)d_in[15];
    const float* Winitc   = (const float*)d_in[16];
    const float* binitc   = (const float*)d_in[17];
    const float* Wbeta    = (const float*)d_in[18];
    const float* bbeta    = (const float*)d_in[19];
    const float* Wfin     = (const float*)d_in[20];
    const float* bfin     = (const float*)d_in[21];
    float* out = (float*)d_out;

    cudaFuncSetAttribute(s_encatt, cudaFuncAttributeMaxDynamicSharedMemorySize, EA_SMEM);

    cudaMemsetAsync(d_out, 0, (size_t)out_size*sizeof(float), 0);

    s_init<<<BB, 512>>>(enc, lens, Winith, binith, Winitc, binitc, out);
    s_encatt<<<(BB*VV)/32, 256, EA_SMEM>>>(enc, Wenc, benc);

    for (int t = 0; t < TT; t++) {
        k1_head<<<dim3(26,4), 256>>>(t, Wdec, bdec, Wbeta, bbeta, Wfin, bfin, lens, out);
        k23_attn<<<BB, 512>>>(t, captions, embW, wfull, lens, out);
        k4_lstm<<<dim3(64,2), 256>>>(t, Wih, bih, Whh, bhh, lens);
    }
    k1_head<<<dim3(26,4), 256>>>(TT, Wdec, bdec, Wbeta, bbeta, Wfin, bfin, lens, out);
}

// round 4
// speedup vs baseline: 1.9604x; 1.9604x over previous
#include <cuda_runtime.h>
#include <cuda_fp16.h>
#include <math.h>

#define BB   64
#define VV   2048
#define ENCD 128
#define TT   100
#define EMBD 256
#define DECD 512
#define ATTD 256
#define NVOC 29
#define XD   384   // EMB + ENC
#define NCH  16    // V-chunks of 128

#define PRED_OFF  0
#define ALPHA_OFF (BB*TT*NVOC)            // 185600
#define LEN_OFF   (ALPHA_OFF + BB*TT*VV)  // 13292800

// ---------------- scratch (device globals; no allocation allowed) ----------
__device__ __half g_enc_att_h[BB*VV*ATTD];  // 64 MB fp16
__device__ __half g_enc_h[BB*VV*ENCD];      // 32 MB fp16
__device__ float  g_hbuf[2][BB*DECD];
__device__ float  g_c[BB*DECD];
__device__ float  g_dec_att[BB*ATTD];
__device__ float  g_gate[BB*ENCD];
__device__ float  g_scores[BB*VV];
__device__ float  g_pmax[BB*NCH];
__device__ float  g_psum[BB*NCH];
__device__ float  g_awe_part[BB*NCH*ENCD];  // 512 KB
__device__ float  g_x[BB*XD];

__device__ __forceinline__ float sigf(float x) { return 1.f/(1.f+__expf(-x)); }

// ============================================================================
// Setup A: mean_enc -> h0,c0 ; lengths to out tail
// ============================================================================
__global__ void s_init(const float* __restrict__ enc, const int* __restrict__ lens,
                       const float* __restrict__ Wih_, const float* __restrict__ bih_,
                       const float* __restrict__ Wic_, const float* __restrict__ bic_,
                       float* __restrict__ out)
{
    int b = blockIdx.x, tid = threadIdx.x;
    __shared__ float red[16*128];
    __shared__ float mean[128];
    int vr = tid >> 5, l = tid & 31;

    float4 acc = make_float4(0.f,0.f,0.f,0.f);
    for (int v = vr; v < VV; v += 16) {
        float4 e = *(const float4*)&enc[((size_t)(b*VV + v))*ENCD + l*4];
        acc.x += e.x; acc.y += e.y; acc.z += e.z; acc.w += e.w;
    }
    *(float4*)&red[vr*128 + l*4] = acc;
    __syncthreads();
    if (tid < 128) {
        float s = 0.f;
        #pragma unroll
        for (int i = 0; i < 16; i++) s += red[i*128 + tid];
        mean[tid] = s * (1.f/(float)VV);
    }
    __syncthreads();
    float ha = bih_[tid], ca = bic_[tid];
    const float* wh = Wih_ + (size_t)tid*ENCD;
    const float* wc = Wic_ + (size_t)tid*ENCD;
    #pragma unroll 4
    for (int k = 0; k < ENCD; k++) {
        float mk = mean[k];
        ha += mk * wh[k];
        ca += mk * wc[k];
    }
    g_hbuf[0][b*DECD + tid] = ha;
    g_c[b*DECD + tid] = ca;
    if (tid == 0) out[LEN_OFF + b] = (float)lens[b];
}

// ============================================================================
// Setup B: enc_att(fp16) = enc @ W_enc.T + b_enc ; fp16 enc copy
// ============================================================================
#define EA_SMEM ((128*264 + 128*68)*4)
__global__ void __launch_bounds__(256)
s_encatt(const float* __restrict__ enc, const float* __restrict__ Wenc,
         const float* __restrict__ benc)
{
    extern __shared__ float sm[];
    float* Wt = sm;             // [128][264]
    float* Et = sm + 128*264;   // [128][68]
    int tid = threadIdx.x;
    int rowbase = blockIdx.x * 32;

    for (int i = tid; i < 256*128; i += 256) {
        int k = i & 127, a = i >> 7;
        Wt[k*264 + a] = Wenc[a*128 + k];
    }
    for (int i = tid; i < 32*128; i += 256) {
        int k = i & 127, r = i >> 7;
        Et[k*68 + r] = enc[(size_t)(rowbase + r)*128 + k];
    }
    __syncthreads();

    for (int i = tid; i < 32*128; i += 256) {
        int r = i >> 7, k = i & 127;
        g_enc_h[(size_t)(rowbase + r)*ENCD + k] = __float2half_rn(Et[k*68 + r]);
    }

    int tr = tid >> 5, ta = tid & 31;
    int r0 = tr*4, a0 = ta*8;
    float acc[4][8];
    #pragma unroll
    for (int i = 0; i < 4; i++)
        #pragma unroll
        for (int j = 0; j < 8; j++) acc[i][j] = 0.f;

    #pragma unroll 4
    for (int k = 0; k < 128; k++) {
        float4 rf = *(const float4*)&Et[k*68 + r0];
        float4 a4 = *(const float4*)&Wt[k*264 + a0];
        float4 b4 = *(const float4*)&Wt[k*264 + a0 + 4];
        float rr[4] = {rf.x, rf.y, rf.z, rf.w};
        float aa[8] = {a4.x,a4.y,a4.z,a4.w,b4.x,b4.y,b4.z,b4.w};
        #pragma unroll
        for (int i = 0; i < 4; i++)
            #pragma unroll
            for (int j = 0; j < 8; j++) acc[i][j] += rr[i]*aa[j];
    }
    float4 be0 = *(const float4*)&benc[a0];
    float4 be1 = *(const float4*)&benc[a0+4];
    float bb[8] = {be0.x,be0.y,be0.z,be0.w,be1.x,be1.y,be1.z,be1.w};
    #pragma unroll
    for (int i = 0; i < 4; i++) {
        size_t base = (size_t)(rowbase + r0 + i)*ATTD + a0;
        __half2 h[4];
        #pragma unroll
        for (int j = 0; j < 4; j++)
            h[j] = __floats2half2_rn(acc[i][2*j] + bb[2*j], acc[i][2*j+1] + bb[2*j+1]);
        *(uint4*)&g_enc_att_h[base] = *(uint4*)h;
    }
}

// ============================================================================
// K1: dec_att / gate / pred_{t-1}
// ============================================================================
__global__ void __launch_bounds__(256)
k1_head(int t,
        const float* __restrict__ Wdec, const float* __restrict__ bdec,
        const float* __restrict__ Wbeta, const float* __restrict__ bbeta,
        const float* __restrict__ Wfin, const float* __restrict__ bfin,
        const int* __restrict__ lens, float* __restrict__ out)
{
    __shared__ float hT[512*17];
    int tid = threadIdx.x;
    int p = t & 1;
    int bg = blockIdx.y;
    int rr = blockIdx.x*16 + (tid >> 4);
    int lane = tid & 15;
    int b = bg*16 + lane;

    const float* hsrc = g_hbuf[p];
    for (int i = tid; i < 16*512; i += 256) {
        int bl = i >> 9, k = i & 511;
        hT[k*17 + bl] = hsrc[(bg*16 + bl)*DECD + k];
    }
    __syncthreads();

    const float* wrow = nullptr; float bias = 0.f;
    if (rr < 256)      { wrow = Wdec  + (size_t)rr*DECD;       bias = bdec[rr]; }
    else if (rr < 384) { wrow = Wbeta + (size_t)(rr-256)*DECD; bias = bbeta[rr-256]; }
    else if (rr < 384+NVOC) { wrow = Wfin + (size_t)(rr-384)*DECD; bias = bfin[rr-384]; }

    if (wrow) {
        float acc = bias;
        #pragma unroll 4
        for (int k = 0; k < 512; k += 4) {
            float4 w = *(const float4*)&wrow[k];
            acc += w.x*hT[(k  )*17 + lane] + w.y*hT[(k+1)*17 + lane]
                 + w.z*hT[(k+2)*17 + lane] + w.w*hT[(k+3)*17 + lane];
        }
        if (rr < 256) {
            g_dec_att[b*ATTD + rr] = acc;
        } else if (rr < 384) {
            g_gate[b*ENCD + (rr-256)] = sigf(acc);
        } else {
            if (t > 0 && (t-1) < lens[b])
                out[PRED_OFF + ((size_t)b*TT + (t-1))*NVOC + (rr-384)] = acc;
        }
    }
}

// ============================================================================
// K2: scores (fp16 enc_att) + per-chunk online softmax partials (max, expsum)
// grid(16,64), block 256 = 8 warps; each block: 128 v-rows.
// ============================================================================
__global__ void __launch_bounds__(256)
k2_scores(int t, const float* __restrict__ wfull, const int* __restrict__ lens)
{
    int b = blockIdx.y;
    if (t >= lens[b]) return;
    int tid = threadIdx.x;
    int warp = tid >> 5, l = tid & 31;
    int chunk = blockIdx.x;
    int vbase = chunk*128;

    __shared__ float sc[128];
    __shared__ float wred[8];

    int a0 = l*8;
    float d[8], w[8];
    {
        float4 dd0 = *(const float4*)&g_dec_att[b*ATTD + a0];
        float4 dd1 = *(const float4*)&g_dec_att[b*ATTD + a0 + 4];
        float4 ww0 = *(const float4*)&wfull[a0];
        float4 ww1 = *(const float4*)&wfull[a0 + 4];
        d[0]=dd0.x; d[1]=dd0.y; d[2]=dd0.z; d[3]=dd0.w;
        d[4]=dd1.x; d[5]=dd1.y; d[6]=dd1.z; d[7]=dd1.w;
        w[0]=ww0.x; w[1]=ww0.y; w[2]=ww0.z; w[3]=ww0.w;
        w[4]=ww1.x; w[5]=ww1.y; w[6]=ww1.z; w[7]=ww1.w;
    }
    const __half* ea = g_enc_att_h + ((size_t)(b*VV + vbase))*ATTD;

    // 16 rows per warp, 2 in flight
    #pragma unroll 2
    for (int i = 0; i < 16; i += 2) {
        int r0 = (i  )*8 + warp;
        int r1 = (i+1)*8 + warp;
        uint4 q0 = *(const uint4*)&ea[(size_t)r0*ATTD + a0];
        uint4 q1 = *(const uint4*)&ea[(size_t)r1*ATTD + a0];
        const __half2* h0 = (const __half2*)&q0;
        const __half2* h1 = (const __half2*)&q1;
        float s0 = 0.f, s1 = 0.f;
        #pragma unroll
        for (int j = 0; j < 4; j++) {
            float2 e0 = __half22float2(h0[j]);
            float2 e1 = __half22float2(h1[j]);
            s0 += fmaxf(e0.x + d[2*j],   0.f)*w[2*j]
                + fmaxf(e0.y + d[2*j+1], 0.f)*w[2*j+1];
            s1 += fmaxf(e1.x + d[2*j],   0.f)*w[2*j]
                + fmaxf(e1.y + d[2*j+1], 0.f)*w[2*j+1];
        }
        #pragma unroll
        for (int o = 16; o; o >>= 1) {
            s0 += __shfl_xor_sync(0xffffffffu, s0, o);
            s1 += __shfl_xor_sync(0xffffffffu, s1, o);
        }
        if (l == 0) { sc[r0] = s0; sc[r1] = s1; }
    }
    __syncthreads();

    // block max over 128
    float m = (tid < 128) ? sc[tid] : -1e30f;
    #pragma unroll
    for (int o = 16; o; o >>= 1) m = fmaxf(m, __shfl_xor_sync(0xffffffffu, m, o));
    if (l == 0) wred[warp] = m;
    __syncthreads();
    float bmax = wred[0];
    #pragma unroll
    for (int i = 1; i < 8; i++) bmax = fmaxf(bmax, wred[i]);

    // block expsum
    float e = (tid < 128) ? __expf(sc[tid] - bmax) : 0.f;
    #pragma unroll
    for (int o = 16; o; o >>= 1) e += __shfl_xor_sync(0xffffffffu, e, o);
    __syncthreads();
    if (l == 0) wred[warp] = e;
    __syncthreads();

    if (tid < 128) g_scores[b*VV + vbase + tid] = sc[tid];
    if (tid == 0) {
        float ss = 0.f;
        #pragma unroll
        for (int i = 0; i < 8; i++) ss += wred[i];
        g_pmax[b*NCH + chunk] = bmax;
        g_psum[b*NCH + chunk] = ss;
    }
}

// ============================================================================
// K4: combine partials -> alpha (write to out) -> partial awe per chunk
// grid(16,64), block 256 = 8 warps.
// ============================================================================
__global__ void __launch_bounds__(256)
k4_awe(int t, const int* __restrict__ lens, float* __restrict__ out)
{
    int b = blockIdx.y;
    if (t >= lens[b]) return;
    int tid = threadIdx.x;
    int warp = tid >> 5, l = tid & 31;
    int chunk = blockIdx.x;
    int vbase = chunk*128;

    __shared__ float al[128];
    __shared__ float red[8*128];

    // combine softmax stats (16 values)
    float M = -1e30f;
    #pragma unroll
    for (int i = 0; i < NCH; i++) M = fmaxf(M, g_pmax[b*NCH + i]);
    float S = 0.f;
    #pragma unroll
    for (int i = 0; i < NCH; i++) S += g_psum[b*NCH + i] * __expf(g_pmax[b*NCH + i] - M);
    float inv = 1.f/S;

    if (tid < 128) {
        float a = __expf(g_scores[b*VV + vbase + tid] - M) * inv;
        al[tid] = a;
        out[ALPHA_OFF + ((size_t)b*TT + t)*VV + vbase + tid] = a;
    }
    __syncthreads();

    // partial awe over 128 rows: warp -> 16 rows, lane -> 4 enc dims
    const __half* eh = g_enc_h + ((size_t)(b*VV + vbase))*ENCD;
    float4 acc = make_float4(0.f,0.f,0.f,0.f);
    #pragma unroll 4
    for (int i = 0; i < 16; i++) {
        int r = i*8 + warp;
        float a = al[r];
        uint2 q = *(const uint2*)&eh[(size_t)r*ENCD + l*4];
        float2 e0 = __half22float2(((const __half2*)&q)[0]);
        float2 e1 = __half22float2(((const __half2*)&q)[1]);
        acc.x += a*e0.x; acc.y += a*e0.y; acc.z += a*e1.x; acc.w += a*e1.y;
    }
    *(float4*)&red[warp*128 + l*4] = acc;
    __syncthreads();
    if (tid < 128) {
        float s = 0.f;
        #pragma unroll
        for (int i = 0; i < 8; i++) s += red[i*128 + tid];
        g_awe_part[(b*NCH + chunk)*ENCD + tid] = s;
    }
}

// ============================================================================
// K5: reduce awe partials, gate, emb lookup -> x.  grid(64), block 256.
// ============================================================================
__global__ void __launch_bounds__(256)
k5_x(int t, const int* __restrict__ captions, const float* __restrict__ embW,
     const int* __restrict__ lens)
{
    int b = blockIdx.x;
    if (t >= lens[b]) return;
    int tid = threadIdx.x;
    if (tid < 128) {
        float s = 0.f;
        #pragma unroll
        for (int i = 0; i < NCH; i++) s += g_awe_part[(b*NCH + i)*ENCD + tid];
        g_x[b*XD + EMBD + tid] = s * g_gate[b*ENCD + tid];
    }
    int cap = captions[b*TT + t];
    g_x[b*XD + tid] = embW[cap*EMBD + tid];
}

// ============================================================================
// K6: LSTM cell.
// ============================================================================
__global__ void __launch_bounds__(256)
k6_lstm(int t,
        const float* __restrict__ Wih, const float* __restrict__ bih,
        const float* __restrict__ Whh, const float* __restrict__ bhh,
        const int* __restrict__ lens)
{
    int jc = blockIdx.x;
    int bh = blockIdx.y;
    int tid = threadIdx.x;
    int p = t & 1;
    int jbase = jc*8;
    int b0 = bh*32;

    if (t >= lens[b0]) {
        int jj = tid >> 5, bl = tid & 31;
        int idx = (b0 + bl)*DECD + jbase + jj;
        g_hbuf[1-p][idx] = g_hbuf[p][idx];
        return;
    }

    __shared__ float zt[128*36];
    __shared__ float ws[32*132];
    __shared__ float gs[32*33];

    int r = tid >> 3;
    int lane = tid & 7;
    int bl0 = lane*4;
    int grow = (r >> 3)*DECD + jbase + (r & 7);

    float acc0=0.f, acc1=0.f, acc2=0.f, acc3=0.f;
    const float* hsrc = g_hbuf[p];

    for (int kt = 0; kt < 7; kt++) {
        for (int i = tid; i < 32*128; i += 256) {
            int bl = i >> 7, k = i & 127;
            float v;
            if (kt < 3) v = g_x[(b0 + bl)*XD + kt*128 + k];
            else        v = hsrc[(b0 + bl)*DECD + (kt-3)*128 + k];
            zt[k*36 + bl] = v;
        }
        const float* Wp = (kt < 3) ? Wih : Whh;
        int kstride = (kt < 3) ? XD : DECD;
        int kb = (kt < 3) ? kt*128 : (kt-3)*128;
        for (int i = tid; i < 32*128; i += 256) {
            int rr2 = i >> 7, k = i & 127;
            int gr = (rr2 >> 3)*DECD + jbase + (rr2 & 7);
            ws[rr2*132 + k] = Wp[(size_t)gr*kstride + kb + k];
        }
        __syncthreads();
        #pragma unroll 4
        for (int k = 0; k < 128; k += 4) {
            float4 w4 = *(const float4*)&ws[r*132 + k];
            float4 za = *(const float4*)&zt[(k  )*36 + bl0];
            float4 zb = *(const float4*)&zt[(k+1)*36 + bl0];
            float4 zc = *(const float4*)&zt[(k+2)*36 + bl0];
            float4 zd = *(const float4*)&zt[(k+3)*36 + bl0];
            acc0 += w4.x*za.x + w4.y*zb.x + w4.z*zc.x + w4.w*zd.x;
            acc1 += w4.x*za.y + w4.y*zb.y + w4.z*zc.y + w4.w*zd.y;
            acc2 += w4.x*za.z + w4.y*zb.z + w4.z*zc.z + w4.w*zd.z;
            acc3 += w4.x*za.w + w4.y*zb.w + w4.z*zc.w + w4.w*zd.w;
        }
        __syncthreads();
    }
    float bias = bih[grow] + bhh[grow];
    gs[r*33 + bl0 + 0] = acc0 + bias;
    gs[r*33 + bl0 + 1] = acc1 + bias;
    gs[r*33 + bl0 + 2] = acc2 + bias;
    gs[r*33 + bl0 + 3] = acc3 + bias;
    __syncthreads();

    {
        int jj = tid >> 5, bl = tid & 31;
        int b = b0 + bl;
        int hidx = b*DECD + jbase + jj;
        if (t < lens[b]) {
            float gi = gs[( 0 + jj)*33 + bl];
            float gf = gs[( 8 + jj)*33 + bl];
            float gg = gs[(16 + jj)*33 + bl];
            float go = gs[(24 + jj)*33 + bl];
            float si = sigf(gi), sf = sigf(gf), so = sigf(go);
            float tg = tanhf(gg);
            float cn = sf * g_c[hidx] + si * tg;
            float hn = so * tanhf(cn);
            g_c[hidx] = cn;
            g_hbuf[1-p][hidx] = hn;
        } else {
            g_hbuf[1-p][hidx] = g_hbuf[p][hidx];
        }
    }
}

// ============================================================================
extern "C" void kernel_launch(void* const* d_in, const int* in_sizes, int n_in,
                              void* d_out, int out_size)
{
    const float* enc      = (const float*)d_in[0];
    const int*   captions = (const int*)  d_in[1];
    const int*   lens     = (const int*)  d_in[2];
    const float* embW     = (const float*)d_in[3];
    const float* Wenc     = (const float*)d_in[4];
    const float* benc     = (const float*)d_in[5];
    const float* Wdec     = (const float*)d_in[6];
    const float* bdec     = (const float*)d_in[7];
    const float* wfull    = (const float*)d_in[8];
    // d_in[9] = b_full : dropped (softmax shift-invariant)
    const float* Wih      = (const float*)d_in[10];
    const float* bih      = (const float*)d_in[11];
    const float* Whh      = (const float*)d_in[12];
    const float* bhh      = (const float*)d_in[13];
    const float* Winith   = (const float*)d_in[14];
    const float* binith   = (const float*)d_in[15];
    const float* Winitc   = (const float*)d_in[16];
    const float* binitc   = (const float*)d_in[17];
    const float* Wbeta    = (const float*)d_in[18];
    const float* bbeta    = (const float*)d_in[19];
    const float* Wfin     = (const float*)d_in[20];
    const float* bfin     = (const float*)d_in[21];
    float* out = (float*)d_out;

    cudaFuncSetAttribute(s_encatt, cudaFuncAttributeMaxDynamicSharedMemorySize, EA_SMEM);

    cudaMemsetAsync(d_out, 0, (size_t)out_size*sizeof(float), 0);

    s_init<<<BB, 512>>>(enc, lens, Winith, binith, Winitc, binitc, out);
    s_encatt<<<(BB*VV)/32, 256, EA_SMEM>>>(enc, Wenc, benc);

    for (int t = 0; t < TT; t++) {
        k1_head<<<dim3(26,4), 256>>>(t, Wdec, bdec, Wbeta, bbeta, Wfin, bfin, lens, out);
        k2_scores<<<dim3(NCH,BB), 256>>>(t, wfull, lens);
        k4_awe<<<dim3(NCH,BB), 256>>>(t, lens, out);
        k5_x<<<BB, 256>>>(t, captions, embW, lens);
        k6_lstm<<<dim3(64,2), 256>>>(t, Wih, bih, Whh, bhh, lens);
    }
    k1_head<<<dim3(26,4), 256>>>(TT, Wdec, bdec, Wbeta, bbeta, Wfin, bfin, lens, out);
}